// round 1
// baseline (speedup 1.0000x reference)
#include <cuda_runtime.h>
#include <math.h>

#define NDIM 256
#define BATCH 65536
#define NROT 32640   // 256*255/2

// ---------------- device scratch (no allocs allowed) ----------------
__device__ float g_cs1[NROT], g_sn1[NROT], g_cs2[NROT], g_sn2[NROT];
__device__ float g_cph[NDIM], g_sph[NDIM];
__device__ float g_M1[NDIM * NDIM];   // M1[m][k]
__device__ float g_M2[NDIM * NDIM];   // M2[j][m]
__device__ float g_Wp[NDIM * 2 * NDIM]; // Wp[k][2*j+p], p=0 real, p=1 imag (row stride 512)
__device__ float g_invn2[BATCH];

// ---------------- 1) sincos tables ----------------
__global__ void prep_kernel(const float* __restrict__ rots1,
                            const float* __restrict__ phases,
                            const float* __restrict__ rots2) {
    int idx = blockIdx.x * blockDim.x + threadIdx.x;
    if (idx < NROT) {
        float s, c;
        sincosf(rots1[idx], &s, &c); g_sn1[idx] = s; g_cs1[idx] = c;
        sincosf(rots2[idx], &s, &c); g_sn2[idx] = s; g_cs2[idx] = c;
    }
    if (idx < NDIM) {
        float s, c;
        sincosf(phases[idx], &s, &c); g_sph[idx] = s; g_cph[idx] = c;
    }
}

// ---------------- 2) Givens build ----------------
// M = G_last @ ... @ G_1 @ I. Each COLUMN of M evolves independently:
// rotation (i,j,th) does  m[i] <- c*m[i]-s*m[j],  m[j] <- s*m[i]+c*m[j].
// 4 blocks: (matrix 0/1) x (column half 0/1); 128 threads = 128 columns.
// Thread owns its column in smem -> no __syncthreads in the 32640-step loop.
// Row i is register-cached across its run of j's, so the serial chain is FMA-only.
__global__ void givens_kernel() {
    extern __shared__ float sm[];          // [NDIM][128]
    const int mat  = blockIdx.x >> 1;
    const int half = blockIdx.x & 1;
    const int t    = threadIdx.x;          // 0..127
    const int col  = half * 128 + t;

    const float* __restrict__ cs = mat ? g_cs2 : g_cs1;
    const float* __restrict__ sn = mat ? g_sn2 : g_sn1;
    float* __restrict__ M = mat ? g_M2 : g_M1;

    for (int row = 0; row < NDIM; row++)
        sm[row * 128 + t] = (row == col) ? 1.0f : 0.0f;

    int r = 0;
    for (int i = 0; i < NDIM - 1; i++) {
        float a = sm[i * 128 + t];
        for (int j = i + 1; j < NDIM; j++, r++) {
            float c = __ldg(&cs[r]);
            float s = __ldg(&sn[r]);
            float b = sm[j * 128 + t];
            sm[j * 128 + t] = fmaf(s, a, c * b);
            a = fmaf(c, a, -s * b);
        }
        sm[i * 128 + t] = a;
    }

    for (int row = 0; row < NDIM; row++)
        M[row * NDIM + col] = sm[row * 128 + t];
}

// ---------------- 3) compose T = M2 @ diag(e^{i phi}) @ M1 ----------------
// Tr[j][k] = sum_m M2[j][m]*cos(ph[m])*M1[m][k]; Ti with sin.
// Stored interleaved: Wp[k][2j] = Tr[j][k], Wp[k][2j+1] = Ti[j][k].
// 32 blocks x 256 threads; block covers 8 j's; thread = one k.
__global__ void compose_kernel() {
    __shared__ float smT[NDIM][17];        // [k][16 cols] staging for coalesced stores
    const int k  = threadIdx.x;
    const int j0 = blockIdx.x * 8;

    float accr[8], acci[8];
#pragma unroll
    for (int jj = 0; jj < 8; jj++) { accr[jj] = 0.0f; acci[jj] = 0.0f; }

    for (int m = 0; m < NDIM; m++) {
        float v  = g_M1[m * NDIM + k];     // coalesced
        float br = v * g_cph[m];
        float bi = v * g_sph[m];
#pragma unroll
        for (int jj = 0; jj < 8; jj++) {
            float a = g_M2[(j0 + jj) * NDIM + m];  // uniform broadcast, L1/L2 hot
            accr[jj] = fmaf(a, br, accr[jj]);
            acci[jj] = fmaf(a, bi, acci[jj]);
        }
    }
#pragma unroll
    for (int jj = 0; jj < 8; jj++) {
        smT[k][2 * jj]     = accr[jj];
        smT[k][2 * jj + 1] = acci[jj];
    }
    __syncthreads();
    for (int idx = threadIdx.x; idx < NDIM * 16; idx += 256) {
        int kk = idx >> 4, c = idx & 15;
        g_Wp[kk * 512 + 2 * j0 + c] = smT[kk][c];
    }
}

// ---------------- 4) row inverse-squared-norms ----------------
__global__ void norm_kernel(const float* __restrict__ x) {
    int row  = blockIdx.x * 8 + (threadIdx.x >> 5);
    int lane = threadIdx.x & 31;
    const float4* xr = (const float4*)(x + (size_t)row * NDIM);
    float4 v = xr[lane];
    float s = v.x * v.x + v.y * v.y + v.z * v.z + v.w * v.w;
    v = xr[lane + 32];
    s += v.x * v.x + v.y * v.y + v.z * v.z + v.w * v.w;
#pragma unroll
    for (int o = 16; o; o >>= 1) s += __shfl_xor_sync(0xffffffffu, s, o);
    if (lane == 0) g_invn2[row] = 1.0f / s;
}

// ---------------- 5) GEMM + fused |.|^2 / ||x||^2 epilogue ----------------
// C[65536, 512] = X[65536,256] @ Wp[256,512]; out[b,j] = (C[b,2j]^2 + C[b,2j+1]^2)*invn2[b]
#define BM 128
#define BN 128
#define BK 16

__global__ void __launch_bounds__(256) gemm_kernel(const float* __restrict__ X,
                                                   float* __restrict__ out) {
    __shared__ float Xs[BK][BM + 4];
    __shared__ float Ws[BK][BN];

    const int n0 = blockIdx.x * BN;
    const int m0 = blockIdx.y * BM;
    const int tid = threadIdx.x;
    const int tx = tid & 15, ty = tid >> 4;

    float acc[8][8];
#pragma unroll
    for (int i = 0; i < 8; i++)
#pragma unroll
        for (int j = 0; j < 8; j++) acc[i][j] = 0.0f;

    const int lrow = tid >> 2;          // 0..63
    const int lc4  = (tid & 3) * 4;     // 0,4,8,12
    const int wk   = tid >> 5;          // 0..7
    const int wn4  = (tid & 31) * 4;    // 0..124

    for (int k0 = 0; k0 < NDIM; k0 += BK) {
        float4 xa = *(const float4*)(X + (size_t)(m0 + lrow) * NDIM + k0 + lc4);
        float4 xb = *(const float4*)(X + (size_t)(m0 + lrow + 64) * NDIM + k0 + lc4);
        float4 wa = *(const float4*)(g_Wp + (k0 + wk) * 512 + n0 + wn4);
        float4 wb = *(const float4*)(g_Wp + (k0 + wk + 8) * 512 + n0 + wn4);
        __syncthreads();
        Xs[lc4 + 0][lrow] = xa.x; Xs[lc4 + 1][lrow] = xa.y;
        Xs[lc4 + 2][lrow] = xa.z; Xs[lc4 + 3][lrow] = xa.w;
        Xs[lc4 + 0][lrow + 64] = xb.x; Xs[lc4 + 1][lrow + 64] = xb.y;
        Xs[lc4 + 2][lrow + 64] = xb.z; Xs[lc4 + 3][lrow + 64] = xb.w;
        *(float4*)&Ws[wk][wn4]     = wa;
        *(float4*)&Ws[wk + 8][wn4] = wb;
        __syncthreads();
#pragma unroll
        for (int kk = 0; kk < BK; kk++) {
            float a[8], b[8];
            *(float4*)(a)     = *(const float4*)&Xs[kk][ty * 8];
            *(float4*)(a + 4) = *(const float4*)&Xs[kk][ty * 8 + 4];
            *(float4*)(b)     = *(const float4*)&Ws[kk][tx * 8];
            *(float4*)(b + 4) = *(const float4*)&Ws[kk][tx * 8 + 4];
#pragma unroll
            for (int i = 0; i < 8; i++)
#pragma unroll
                for (int j = 0; j < 8; j++)
                    acc[i][j] = fmaf(a[i], b[j], acc[i][j]);
        }
    }

    // epilogue: pairs (2j, 2j+1) -> (r,i); out col = n/2
    const int jout0 = (n0 >> 1) + tx * 4;
#pragma unroll
    for (int i = 0; i < 8; i++) {
        int m = m0 + ty * 8 + i;
        float inv = g_invn2[m];
        float4 o;
        o.x = (acc[i][0] * acc[i][0] + acc[i][1] * acc[i][1]) * inv;
        o.y = (acc[i][2] * acc[i][2] + acc[i][3] * acc[i][3]) * inv;
        o.z = (acc[i][4] * acc[i][4] + acc[i][5] * acc[i][5]) * inv;
        o.w = (acc[i][6] * acc[i][6] + acc[i][7] * acc[i][7]) * inv;
        *(float4*)(out + (size_t)m * NDIM + jout0) = o;
    }
}

// ---------------- launch ----------------
extern "C" void kernel_launch(void* const* d_in, const int* in_sizes, int n_in,
                              void* d_out, int out_size) {
    const float* x      = (const float*)d_in[0];
    const float* rots1  = (const float*)d_in[1];
    const float* phases = (const float*)d_in[2];
    const float* rots2  = (const float*)d_in[3];
    float* out = (float*)d_out;

    static bool attr_done = false;
    if (!attr_done) {
        cudaFuncSetAttribute(givens_kernel,
                             cudaFuncAttributeMaxDynamicSharedMemorySize,
                             NDIM * 128 * (int)sizeof(float));
        attr_done = true;
    }

    prep_kernel<<<(NROT + 255) / 256, 256>>>(rots1, phases, rots2);
    givens_kernel<<<4, 128, NDIM * 128 * sizeof(float)>>>();
    compose_kernel<<<NDIM / 8, 256>>>();
    norm_kernel<<<BATCH / 8, 256>>>(x);
    dim3 grid(2 * NDIM / BN, BATCH / BM);
    gemm_kernel<<<grid, 256>>>(x, out);
}